// round 1
// baseline (speedup 1.0000x reference)
#include <cuda_runtime.h>
#include <cstdint>
#include <cstddef>

// Problem constants
#define B_   16
#define N_   2048
#define E_   32768
#define D_   256
#define R_   8
#define L_   2

#define M_TOT (B_ * N_)      // 32768 rows
#define K1    (R_ * D_)      // 2048 (relation part of K)

// ---------------- scratch (device globals; no allocation allowed) ----------
__device__ float g_x[M_TOT * D_];                 // layer input  (33.5 MB)
__device__ float g_y[M_TOT * D_];                 // layer output (33.5 MB)
__device__ float g_acc[(size_t)M_TOT * K1];       // (32768, 2048) = 268 MB
__device__ float g_deg[M_TOT];

// ---------------- packed f32x2 helpers (Blackwell) --------------------------
__device__ __forceinline__ unsigned long long pack2(float lo, float hi) {
    unsigned long long r;
    asm("mov.b64 %0, {%1, %2};" : "=l"(r) : "f"(lo), "f"(hi));
    return r;
}
__device__ __forceinline__ void fma2(unsigned long long& c,
                                     unsigned long long a,
                                     unsigned long long b) {
    asm("fma.rn.f32x2 %0, %1, %2, %0;" : "+l"(c) : "l"(a), "l"(b));
}
__device__ __forceinline__ void mul2(unsigned long long& c, unsigned long long s) {
    asm("mul.rn.f32x2 %0, %1, %0;" : "+l"(c) : "l"(s));
}
__device__ __forceinline__ void unpack2(unsigned long long v, float& lo, float& hi) {
    asm("mov.b64 {%0, %1}, %2;" : "=f"(lo), "=f"(hi) : "l"(v));
}

// ---------------- kernels ---------------------------------------------------

// x[b,n,:] = emb[nodes[b,n],:]   (float4 granularity)
__global__ void gather_kernel(const int* __restrict__ nodes,
                              const float* __restrict__ emb,
                              float* __restrict__ x) {
    int idx = blockIdx.x * blockDim.x + threadIdx.x;   // over M_TOT * 64 float4
    if (idx >= M_TOT * (D_ / 4)) return;
    int node = idx >> 6;
    int q = idx & 63;
    int v = nodes[node];
    ((float4*)x)[idx] = ((const float4*)emb)[(size_t)v * 64 + q];
}

// zero acc + deg
__global__ void zero_acc_deg() {
    int idx = blockIdx.x * blockDim.x + threadIdx.x;   // 16,777,216 threads
    float4 z = make_float4(0.f, 0.f, 0.f, 0.f);
    ((float4*)g_acc)[idx] = z;
    if (idx < M_TOT / 4) ((float4*)g_deg)[idx] = z;
}

// One warp per edge: acc[(b,dst), type, :] += x[(b,src), :];  deg[b,dst] += 1
__global__ void scatter_kernel(const float* __restrict__ x,
                               const int* __restrict__ edges,
                               const int* __restrict__ types) {
    int gtid = blockIdx.x * blockDim.x + threadIdx.x;
    int w = gtid >> 5;
    int lane = gtid & 31;
    if (w >= B_ * E_) return;
    int b = w >> 15;            // / E_  (E_ = 2^15)
    int e = w & (E_ - 1);
    const int* eb = edges + (size_t)b * 2 * E_;
    int src = eb[e];
    int dst = eb[E_ + e];
    int r = types[(size_t)b * E_ + e];

    const float4* xs = (const float4*)(x + ((size_t)(b * N_ + src)) * D_);
    float* ap = g_acc + ((size_t)(b * N_ + dst) * R_ + r) * D_;

#pragma unroll
    for (int it = 0; it < 2; it++) {
        int q = lane + it * 32;
        float4 v = xs[q];
        asm volatile("red.global.add.v4.f32 [%0], {%1, %2, %3, %4};"
                     :: "l"(ap + q * 4), "f"(v.x), "f"(v.y), "f"(v.z), "f"(v.w)
                     : "memory");
    }
    if (lane == 0) atomicAdd(&g_deg[b * N_ + dst], 1.0f);
}

// Fused layer GEMM:
//   Out = relu?( [acc | x] * [W_l ; W_root] with 1/deg applied to acc-part + bias )
// A-part1: g_acc (32768 x 2048, row-major), A-part2: X (32768 x 256)
// B-part1: Wl (2048 x 256), B-part2: Wr (256 x 256)
#define BM 128
#define BN 128
#define BK 16
#define PAD_A 132

__global__ void __launch_bounds__(256)
rgcn_gemm(const float* __restrict__ X,
          const float* __restrict__ Wl,
          const float* __restrict__ Wr,
          const float* __restrict__ bias,
          float* __restrict__ Out,
          int do_relu) {
    __shared__ float As[2][BK][PAD_A];   // K-major (transposed on store)
    __shared__ float Bs[2][BK][BN];

    const int tid = threadIdx.x;
    const int row0 = blockIdx.y * BM;
    const int col0 = blockIdx.x * BN;
    const int tx = tid & 15;             // 16 col groups
    const int ty = tid >> 4;             // 16 row groups

    // A-load mapping: 512 float4 per tile; thread: (row = tid/4, quad = tid%4) and row+64
    const int arow = tid >> 2;
    const int aq = tid & 3;
    // B-load mapping: k = tid/32 (+8), col4 = (tid%32)*4
    const int bk = tid >> 5;
    const int bc = (tid & 31) * 4;

    const int NT = 144;                  // 128 acc K-tiles + 16 root K-tiles

    unsigned long long c[8][4];
#pragma unroll
    for (int i = 0; i < 8; i++)
#pragma unroll
        for (int j = 0; j < 4; j++) c[i][j] = 0ULL;

    float4 ra0, ra1, rb0, rb1;

    auto loadTile = [&](int kt) {
        const float* Asrc; int lda; int kk; const float* Bsrc;
        if (kt < 128) {
            Asrc = g_acc; lda = K1; kk = kt * BK;
            Bsrc = Wl + (size_t)kt * BK * D_;
        } else {
            Asrc = X; lda = D_; kk = (kt - 128) * BK;
            Bsrc = Wr + (size_t)(kt - 128) * BK * D_;
        }
        const float* abase = Asrc + (size_t)(row0 + arow) * lda + kk + aq * 4;
        ra0 = *(const float4*)abase;
        ra1 = *(const float4*)(abase + (size_t)64 * lda);
        const float* bbase = Bsrc + bk * D_ + col0 + bc;
        rb0 = *(const float4*)bbase;
        rb1 = *(const float4*)(bbase + 8 * D_);
    };

    auto storeTile = [&](int buf) {
        As[buf][aq * 4 + 0][arow] = ra0.x;
        As[buf][aq * 4 + 1][arow] = ra0.y;
        As[buf][aq * 4 + 2][arow] = ra0.z;
        As[buf][aq * 4 + 3][arow] = ra0.w;
        As[buf][aq * 4 + 0][arow + 64] = ra1.x;
        As[buf][aq * 4 + 1][arow + 64] = ra1.y;
        As[buf][aq * 4 + 2][arow + 64] = ra1.z;
        As[buf][aq * 4 + 3][arow + 64] = ra1.w;
        *(float4*)&Bs[buf][bk][bc] = rb0;
        *(float4*)&Bs[buf][bk + 8][bc] = rb1;
    };

    auto compute = [&](int buf) {
#pragma unroll
        for (int k = 0; k < BK; k++) {
            float4 a0 = *(const float4*)&As[buf][k][ty * 4];
            float4 a1 = *(const float4*)&As[buf][k][ty * 4 + 64];
            ulonglong2 b01 = *(const ulonglong2*)&Bs[buf][k][tx * 4];
            ulonglong2 b23 = *(const ulonglong2*)&Bs[buf][k][tx * 4 + 64];
            unsigned long long bb0 = b01.x, bb1 = b01.y;
            unsigned long long bb2 = b23.x, bb3 = b23.y;
            float av[8] = {a0.x, a0.y, a0.z, a0.w, a1.x, a1.y, a1.z, a1.w};
#pragma unroll
            for (int i = 0; i < 8; i++) {
                unsigned long long aa = pack2(av[i], av[i]);
                fma2(c[i][0], aa, bb0);
                fma2(c[i][1], aa, bb1);
                fma2(c[i][2], aa, bb2);
                fma2(c[i][3], aa, bb3);
            }
        }
    };

    loadTile(0);
    storeTile(0);
    __syncthreads();
    int buf = 0;

#pragma unroll 1
    for (int kt = 0; kt < NT; kt++) {
        if (kt + 1 < NT) loadTile(kt + 1);
        compute(buf);
        if (kt == 127) {
            // all relation-K consumed: scale accumulators by 1/max(deg,1)
#pragma unroll
            for (int i = 0; i < 8; i++) {
                int row = row0 + ((i < 4) ? (ty * 4 + i) : (64 + ty * 4 + (i - 4)));
                float s = 1.0f / fmaxf(g_deg[row], 1.0f);
                unsigned long long ss = pack2(s, s);
#pragma unroll
                for (int j = 0; j < 4; j++) mul2(c[i][j], ss);
            }
        }
        if (kt + 1 < NT) {
            buf ^= 1;
            storeTile(buf);
            __syncthreads();
        }
    }

    // epilogue: + bias, optional relu, store
    float4 bi0 = *(const float4*)&bias[col0 + tx * 4];
    float4 bi1 = *(const float4*)&bias[col0 + 64 + tx * 4];
#pragma unroll
    for (int i = 0; i < 8; i++) {
        int row = row0 + ((i < 4) ? (ty * 4 + i) : (64 + ty * 4 + (i - 4)));
        float o[8];
        unpack2(c[i][0], o[0], o[1]);
        unpack2(c[i][1], o[2], o[3]);
        unpack2(c[i][2], o[4], o[5]);
        unpack2(c[i][3], o[6], o[7]);
        float4 r0 = make_float4(o[0] + bi0.x, o[1] + bi0.y, o[2] + bi0.z, o[3] + bi0.w);
        float4 r1 = make_float4(o[4] + bi1.x, o[5] + bi1.y, o[6] + bi1.z, o[7] + bi1.w);
        if (do_relu) {
            r0.x = fmaxf(r0.x, 0.f); r0.y = fmaxf(r0.y, 0.f);
            r0.z = fmaxf(r0.z, 0.f); r0.w = fmaxf(r0.w, 0.f);
            r1.x = fmaxf(r1.x, 0.f); r1.y = fmaxf(r1.y, 0.f);
            r1.z = fmaxf(r1.z, 0.f); r1.w = fmaxf(r1.w, 0.f);
        }
        *(float4*)&Out[(size_t)row * D_ + col0 + tx * 4] = r0;
        *(float4*)&Out[(size_t)row * D_ + col0 + 64 + tx * 4] = r1;
    }
}

// ---------------- launch ----------------------------------------------------
extern "C" void kernel_launch(void* const* d_in, const int* in_sizes, int n_in,
                              void* d_out, int out_size) {
    const int*   nodes = (const int*)d_in[0];
    const int*   edges = (const int*)d_in[1];
    const int*   types = (const int*)d_in[2];
    const float* emb   = (const float*)d_in[3];
    const float* W     = (const float*)d_in[4];
    const float* Wroot = (const float*)d_in[5];
    const float* bias  = (const float*)d_in[6];
    float* out = (float*)d_out;

    float *x0 = nullptr, *x1 = nullptr;
    cudaGetSymbolAddress((void**)&x0, g_x);
    cudaGetSymbolAddress((void**)&x1, g_y);

    gather_kernel<<<(M_TOT * (D_ / 4) + 255) / 256, 256>>>(nodes, emb, x0);

    const float* xin = x0;
    for (int l = 0; l < L_; l++) {
        zero_acc_deg<<<65536, 256>>>();
        scatter_kernel<<<(B_ * E_ * 32) / 256, 256>>>(xin, edges, types);
        float* o = (l == L_ - 1) ? out : x1;
        dim3 grid(D_ / BN, M_TOT / BM);   // (2, 256)
        rgcn_gemm<<<grid, 256>>>(xin,
                                 W + (size_t)l * R_ * D_ * D_,
                                 Wroot + (size_t)l * D_ * D_,
                                 bias + (size_t)l * D_,
                                 o,
                                 (l < L_ - 1) ? 1 : 0);
        xin = o;
    }
}

// round 3
// speedup vs baseline: 1.8974x; 1.8974x over previous
#include <cuda_runtime.h>
#include <cuda_bf16.h>
#include <cstdint>
#include <cstddef>

// Problem constants
#define B_   16
#define N_   2048
#define E_   32768
#define D_   256
#define R_   8
#define L_   2

#define M_TOT (B_ * N_)       // 32768 rows
#define K1    (R_ * D_)       // 2048 (relation part of K)
#define K_TOT (K1 + D_)       // 2304 total K
#define KT2   32              // K per stage
#define NT2   (K_TOT / KT2)   // 72 stages
#define NTA2  (K1 / KT2)      // 64 stages from acc, 8 from x

// ---------------- scratch (device globals; no allocation allowed) ----------
__device__ float g_x[M_TOT * D_];
__device__ float g_y[M_TOT * D_];
__device__ float g_acc[(size_t)M_TOT * K1];        // 268 MB
__device__ float g_deg[M_TOT];
// pre-split, pre-swizzled B tiles: [kt(72)][nb(2)] x 8192 bytes each
__device__ uint8_t g_Bhi[NT2 * 2 * 8192];
__device__ uint8_t g_Blo[NT2 * 2 * 8192];

// ---------------- smem geometry for the GEMM -------------------------------
#define A_STRIDE  80                       // bytes per 32-bf16 A row (padded)
#define SA_BYTES  (128 * A_STRIDE)         // 10240 per A split
#define OFF_ALO   SA_BYTES                 // 10240
#define OFF_B     (2 * SA_BYTES)           // 20480 (128B aligned)
#define OFF_BLO   (OFF_B + 8192)           // 28672
#define STAGE     (OFF_B + 16384)          // 36864
#define SMEM_DYN  (2 * STAGE + 128)        // 73856 (pad for 128B align)

// ---------------- PTX helpers ----------------------------------------------
__device__ __forceinline__ uint32_t smem_u32(const void* p) {
    uint32_t a;
    asm("{ .reg .u64 t; cvta.to.shared.u64 t, %1; cvt.u32.u64 %0, t; }"
        : "=r"(a) : "l"(p));
    return a;
}
__device__ __forceinline__ void ldsm4(uint32_t (&r)[4], uint32_t addr) {
    asm volatile("ldmatrix.sync.aligned.m8n8.x4.shared.b16 {%0,%1,%2,%3}, [%4];"
                 : "=r"(r[0]), "=r"(r[1]), "=r"(r[2]), "=r"(r[3]) : "r"(addr));
}
__device__ __forceinline__ void ldsm4t(uint32_t (&r)[4], uint32_t addr) {
    asm volatile("ldmatrix.sync.aligned.m8n8.x4.trans.shared.b16 {%0,%1,%2,%3}, [%4];"
                 : "=r"(r[0]), "=r"(r[1]), "=r"(r[2]), "=r"(r[3]) : "r"(addr));
}
__device__ __forceinline__ void mma16816(float (&c)[4], const uint32_t (&a)[4],
                                         uint32_t b0, uint32_t b1) {
    asm volatile("mma.sync.aligned.m16n8k16.row.col.f32.bf16.bf16.f32 "
                 "{%0,%1,%2,%3}, {%4,%5,%6,%7}, {%8,%9}, {%0,%1,%2,%3};"
                 : "+f"(c[0]), "+f"(c[1]), "+f"(c[2]), "+f"(c[3])
                 : "r"(a[0]), "r"(a[1]), "r"(a[2]), "r"(a[3]), "r"(b0), "r"(b1));
}
__device__ __forceinline__ void cp16(uint32_t dst, const void* src) {
    asm volatile("cp.async.cg.shared.global [%0], [%1], 16;"
                 :: "r"(dst), "l"(src) : "memory");
}
__device__ __forceinline__ void sts16(uint32_t addr, uint32_t a, uint32_t b,
                                      uint32_t c, uint32_t d) {
    asm volatile("st.shared.v4.b32 [%0], {%1, %2, %3, %4};"
                 :: "r"(addr), "r"(a), "r"(b), "r"(c), "r"(d) : "memory");
}
// split fp32 pair -> bf16 hi pair + bf16 lo pair (packed)
__device__ __forceinline__ void split2(float x0, float x1, uint32_t& h, uint32_t& l) {
    __nv_bfloat162 hb = __floats2bfloat162_rn(x0, x1);
    h = *(uint32_t*)&hb;
    __nv_bfloat162 lb = __floats2bfloat162_rn(x0 - __bfloat162float(hb.x),
                                              x1 - __bfloat162float(hb.y));
    l = *(uint32_t*)&lb;
}

// ---------------- simple kernels --------------------------------------------
__global__ void gather_kernel(const int* __restrict__ nodes,
                              const float* __restrict__ emb,
                              float* __restrict__ x) {
    int idx = blockIdx.x * blockDim.x + threadIdx.x;
    if (idx >= M_TOT * (D_ / 4)) return;
    int node = idx >> 6;
    int q = idx & 63;
    int v = nodes[node];
    ((float4*)x)[idx] = ((const float4*)emb)[(size_t)v * 64 + q];
}

__global__ void zero_acc_deg() {
    int idx = blockIdx.x * blockDim.x + threadIdx.x;
    float4 z = make_float4(0.f, 0.f, 0.f, 0.f);
    ((float4*)g_acc)[idx] = z;
    if (idx < M_TOT / 4) ((float4*)g_deg)[idx] = z;
}

__global__ void scatter_kernel(const float* __restrict__ x,
                               const int* __restrict__ edges,
                               const int* __restrict__ types) {
    int gtid = blockIdx.x * blockDim.x + threadIdx.x;
    int w = gtid >> 5;
    int lane = gtid & 31;
    if (w >= B_ * E_) return;
    int b = w >> 15;
    int e = w & (E_ - 1);
    const int* eb = edges + (size_t)b * 2 * E_;
    int src = eb[e];
    int dst = eb[E_ + e];
    int r = types[(size_t)b * E_ + e];

    const float4* xs = (const float4*)(x + ((size_t)(b * N_ + src)) * D_);
    float* ap = g_acc + ((size_t)(b * N_ + dst) * R_ + r) * D_;

#pragma unroll
    for (int it = 0; it < 2; it++) {
        int q = lane + it * 32;
        float4 v = xs[q];
        asm volatile("red.global.add.v4.f32 [%0], {%1, %2, %3, %4};"
                     :: "l"(ap + q * 4), "f"(v.x), "f"(v.y), "f"(v.z), "f"(v.w)
                     : "memory");
    }
    if (lane == 0) atomicAdd(&g_deg[b * N_ + dst], 1.0f);
}

// Pre-split + pre-swizzle W into ldmatrix-ready tile images.
// Logical B[k][n] = (k < K1) ? Wl[k][n] : Wr[k-K1][n].
// Tile (kt, nb) image: [krow 0..31][granule g 0..15] with granule swizzle
//   byte_off = krow*256 + ((g ^ (krow & 7)) * 16), covering n = nb*128 + g*8 .. +7
__global__ void bsplit_kernel(const float* __restrict__ Wl,
                              const float* __restrict__ Wr) {
    int gid = blockIdx.x * blockDim.x + threadIdx.x;   // NT2*2*512
    if (gid >= NT2 * 2 * 512) return;
    int tile = gid >> 9;            // kt*2 + nb
    int rem = gid & 511;
    int krow = rem >> 4;
    int g = rem & 15;
    int kt = tile >> 1;
    int nb = tile & 1;
    int k = kt * KT2 + krow;
    int n0 = nb * 128 + g * 8;
    const float* src = (k < K1) ? (Wl + (size_t)k * D_ + n0)
                                : (Wr + (size_t)(k - K1) * D_ + n0);
    float4 v0 = ((const float4*)src)[0];
    float4 v1 = ((const float4*)src)[1];
    uint4 h, l;
    split2(v0.x, v0.y, h.x, l.x);
    split2(v0.z, v0.w, h.y, l.y);
    split2(v1.x, v1.y, h.z, l.z);
    split2(v1.z, v1.w, h.w, l.w);
    uint32_t off = (uint32_t)tile * 8192u + (uint32_t)krow * 256u +
                   ((uint32_t)(g ^ (krow & 7)) << 4);
    *(uint4*)(g_Bhi + off) = h;
    *(uint4*)(g_Blo + off) = l;
}

// ---------------- warp-MMA GEMM ----------------------------------------------
// Out[m0..+127][col0..+127] = relu?( [acc*invdeg | x](K=2304) * B + bias )
// 3-pass bf16 split: ahi*bhi + alo*bhi + ahi*blo, fp32 accum via HMMA.
__global__ void __launch_bounds__(256, 2)
rgcn_gemm_mma(const float* __restrict__ X,
              const float* __restrict__ bias,
              float* __restrict__ Out,
              int do_relu) {
    extern __shared__ uint8_t smem_raw[];
    const uint32_t sbase = (smem_u32(smem_raw) + 127u) & ~127u;

    const int tid = threadIdx.x;
    const int lane = tid & 31;
    const int wid = tid >> 5;
    const int warp_m = wid & 3;      // 4 warps along M (32 rows each)
    const int warp_n = wid >> 2;     // 2 warps along N (64 cols each)
    const int bx = blockIdx.x;
    const int m0 = blockIdx.y * 128;
    const int col0 = bx * 128;

    // A fill mapping: 2 threads per row, 16 k-values each
    const int arow = tid >> 1;
    const int akb = (tid & 1) * 16;
    const float invdeg = 1.0f / fmaxf(g_deg[m0 + arow], 1.0f);
    const uint32_t a_sts = (uint32_t)arow * A_STRIDE + (uint32_t)akb * 2;

    // ldmatrix address pieces
    uint32_t a_off[2];
#pragma unroll
    for (int mt = 0; mt < 2; mt++)
        a_off[mt] = (uint32_t)(warp_m * 32 + mt * 16 + (lane & 15)) * A_STRIDE +
                    (uint32_t)((lane >> 4) * 16);
    const uint32_t krow_base = (uint32_t)((lane & 7) + ((lane >> 3) & 1) * 8);
    uint32_t gg[4];
#pragma unroll
    for (int nt2 = 0; nt2 < 4; nt2++)
        gg[nt2] = (uint32_t)(((warp_n * 8 + nt2 * 2 + (lane >> 4)) ^ (lane & 7)) << 4);

    float c[2][8][4];
#pragma unroll
    for (int mt = 0; mt < 2; mt++)
#pragma unroll
        for (int nt = 0; nt < 8; nt++)
#pragma unroll
            for (int j = 0; j < 4; j++) c[mt][nt][j] = 0.f;

    auto load_stage = [&](int kt, int s) {
        const uint32_t st = sbase + (uint32_t)s * STAGE;
        // B: 4x cp.async of 16B per thread from pre-swizzled tiles
        const uint8_t* bh = g_Bhi + (size_t)(kt * 2 + bx) * 8192 + tid * 16;
        const uint8_t* bl = g_Blo + (size_t)(kt * 2 + bx) * 8192 + tid * 16;
        cp16(st + OFF_B + tid * 16, bh);
        cp16(st + OFF_B + 4096 + tid * 16, bh + 4096);
        cp16(st + OFF_BLO + tid * 16, bl);
        cp16(st + OFF_BLO + 4096 + tid * 16, bl + 4096);
        asm volatile("cp.async.commit_group;" ::: "memory");
        // A: load fp32, scale, split to bf16 hi/lo, store
        const float* asrc;
        float scale;
        if (kt < NTA2) {
            asrc = g_acc + (size_t)(m0 + arow) * K1 + kt * KT2 + akb;
            scale = invdeg;
        } else {
            asrc = X + (size_t)(m0 + arow) * D_ + (kt - NTA2) * KT2 + akb;
            scale = 1.0f;
        }
        uint32_t hi[8], lo[8];
#pragma unroll
        for (int q = 0; q < 4; q++) {
            float4 v = ((const float4*)asrc)[q];
            split2(v.x * scale, v.y * scale, hi[q * 2], lo[q * 2]);
            split2(v.z * scale, v.w * scale, hi[q * 2 + 1], lo[q * 2 + 1]);
        }
        uint32_t ad = st + a_sts;
        sts16(ad, hi[0], hi[1], hi[2], hi[3]);
        sts16(ad + 16, hi[4], hi[5], hi[6], hi[7]);
        sts16(ad + OFF_ALO, lo[0], lo[1], lo[2], lo[3]);
        sts16(ad + OFF_ALO + 16, lo[4], lo[5], lo[6], lo[7]);
    };

    auto compute = [&](int s) {
        const uint32_t st = sbase + (uint32_t)s * STAGE;
#pragma unroll
        for (int k16 = 0; k16 < 2; k16++) {
            const uint32_t kb2 = (uint32_t)(k16 * 32);          // A byte offset
            const uint32_t brow = (uint32_t)((k16 * 16) + krow_base) * 256u;
            uint32_t ah[2][4], al[2][4], bb[4][4];
            // pass 1: ahi * bhi
            ldsm4(ah[0], st + a_off[0] + kb2);
            ldsm4(ah[1], st + a_off[1] + kb2);
#pragma unroll
            for (int nt2 = 0; nt2 < 4; nt2++)
                ldsm4t(bb[nt2], st + OFF_B + brow + gg[nt2]);
#pragma unroll
            for (int mt = 0; mt < 2; mt++)
#pragma unroll
                for (int nt = 0; nt < 8; nt++)
                    mma16816(c[mt][nt], ah[mt], bb[nt >> 1][(nt & 1) * 2],
                             bb[nt >> 1][(nt & 1) * 2 + 1]);
            // pass 2: alo * bhi (reuse bb)
            ldsm4(al[0], st + OFF_ALO + a_off[0] + kb2);
            ldsm4(al[1], st + OFF_ALO + a_off[1] + kb2);
#pragma unroll
            for (int mt = 0; mt < 2; mt++)
#pragma unroll
                for (int nt = 0; nt < 8; nt++)
                    mma16816(c[mt][nt], al[mt], bb[nt >> 1][(nt & 1) * 2],
                             bb[nt >> 1][(nt & 1) * 2 + 1]);
            // pass 3: ahi * blo (reuse ah)
#pragma unroll
            for (int nt2 = 0; nt2 < 4; nt2++)
                ldsm4t(bb[nt2], st + OFF_BLO + brow + gg[nt2]);
#pragma unroll
            for (int mt = 0; mt < 2; mt++)
#pragma unroll
                for (int nt = 0; nt < 8; nt++)
                    mma16816(c[mt][nt], ah[mt], bb[nt >> 1][(nt & 1) * 2],
                             bb[nt >> 1][(nt & 1) * 2 + 1]);
        }
    };

    load_stage(0, 0);
    asm volatile("cp.async.wait_group 0;" ::: "memory");
    __syncthreads();

#pragma unroll 1
    for (int kt = 0; kt < NT2; kt++) {
        const int s = kt & 1;
        if (kt + 1 < NT2) load_stage(kt + 1, s ^ 1);
        compute(s);
        if (kt + 1 < NT2) {
            asm volatile("cp.async.wait_group 0;" ::: "memory");
            __syncthreads();
        }
    }

    // epilogue: + bias, relu?, store fp32
    const int g = lane >> 2;
    const int tc = lane & 3;
#pragma unroll
    for (int mt = 0; mt < 2; mt++) {
        const int row = m0 + warp_m * 32 + mt * 16 + g;
#pragma unroll
        for (int nt = 0; nt < 8; nt++) {
            const int col = col0 + warp_n * 64 + nt * 8 + tc * 2;
            const float b0 = bias[col];
            const float b1 = bias[col + 1];
            float2 v0 = make_float2(c[mt][nt][0] + b0, c[mt][nt][1] + b1);
            float2 v1 = make_float2(c[mt][nt][2] + b0, c[mt][nt][3] + b1);
            if (do_relu) {
                v0.x = fmaxf(v0.x, 0.f); v0.y = fmaxf(v0.y, 0.f);
                v1.x = fmaxf(v1.x, 0.f); v1.y = fmaxf(v1.y, 0.f);
            }
            *(float2*)&Out[(size_t)row * D_ + col] = v0;
            *(float2*)&Out[(size_t)(row + 8) * D_ + col] = v1;
        }
    }
}

// ---------------- launch ----------------------------------------------------
extern "C" void kernel_launch(void* const* d_in, const int* in_sizes, int n_in,
                              void* d_out, int out_size) {
    const int*   nodes = (const int*)d_in[0];
    const int*   edges = (const int*)d_in[1];
    const int*   types = (const int*)d_in[2];
    const float* emb   = (const float*)d_in[3];
    const float* W     = (const float*)d_in[4];
    const float* Wroot = (const float*)d_in[5];
    const float* bias  = (const float*)d_in[6];
    float* out = (float*)d_out;

    cudaFuncSetAttribute(rgcn_gemm_mma,
                         cudaFuncAttributeMaxDynamicSharedMemorySize, SMEM_DYN);

    float *x0 = nullptr, *x1 = nullptr;
    cudaGetSymbolAddress((void**)&x0, g_x);
    cudaGetSymbolAddress((void**)&x1, g_y);

    gather_kernel<<<(M_TOT * (D_ / 4) + 255) / 256, 256>>>(nodes, emb, x0);

    const float* xin = x0;
    for (int l = 0; l < L_; l++) {
        zero_acc_deg<<<65536, 256>>>();
        scatter_kernel<<<(B_ * E_ * 32) / 256, 256>>>(xin, edges, types);
        bsplit_kernel<<<(NT2 * 2 * 512 + 255) / 256, 256>>>(
            W + (size_t)l * R_ * D_ * D_, Wroot + (size_t)l * D_ * D_);
        float* o = (l == L_ - 1) ? out : x1;
        dim3 grid(2, M_TOT / 128);   // (2, 256)
        rgcn_gemm_mma<<<grid, 256, SMEM_DYN>>>(
            xin, bias + (size_t)l * D_, o, (l < L_ - 1) ? 1 : 0);
        xin = o;
    }
}

// round 4
// speedup vs baseline: 2.5356x; 1.3364x over previous
#include <cuda_runtime.h>
#include <cuda_fp16.h>
#include <cstdint>
#include <cstddef>

// Problem constants
#define B_   16
#define N_   2048
#define E_   32768
#define D_   256
#define R_   8
#define L_   2

#define M_TOT (B_ * N_)       // 32768 rows
#define K1    (R_ * D_)       // 2048 (relation part of K)
#define K_TOT (K1 + D_)       // 2304 total K
#define KT2   32              // K per stage
#define NT2   (K_TOT / KT2)   // 72 stages
#define NTA2  (K1 / KT2)      // 64 stages from acc, 8 from x

// ---------------- scratch (device globals; no allocation allowed) ----------
__device__ float g_x[M_TOT * D_];
__device__ float g_y[M_TOT * D_];
__device__ float g_acc[(size_t)M_TOT * K1];        // 268 MB
__device__ float g_deg[M_TOT];
// pre-converted, pre-swizzled fp16 B tiles: [kt(72)][nb(2)] x 8192 bytes each
__device__ uint8_t g_Bh[NT2 * 2 * 8192];

// ---------------- smem geometry for the GEMM -------------------------------
#define A_STRIDE  80                       // bytes per 32-fp16 A row (64B + 16 pad)
#define SA_BYTES  (128 * A_STRIDE)         // 10240 per A split
#define OFF_ALO   SA_BYTES                 // 10240
#define OFF_B     (2 * SA_BYTES)           // 20480 (128B aligned)
#define STAGE     (OFF_B + 8192)           // 28672
#define SMEM_DYN  (2 * STAGE + 128)        // 57472

// ---------------- PTX helpers ----------------------------------------------
__device__ __forceinline__ uint32_t smem_u32(const void* p) {
    uint32_t a;
    asm("{ .reg .u64 t; cvta.to.shared.u64 t, %1; cvt.u32.u64 %0, t; }"
        : "=r"(a) : "l"(p));
    return a;
}
__device__ __forceinline__ void ldsm4(uint32_t (&r)[4], uint32_t addr) {
    asm volatile("ldmatrix.sync.aligned.m8n8.x4.shared.b16 {%0,%1,%2,%3}, [%4];"
                 : "=r"(r[0]), "=r"(r[1]), "=r"(r[2]), "=r"(r[3]) : "r"(addr));
}
__device__ __forceinline__ void ldsm4t(uint32_t (&r)[4], uint32_t addr) {
    asm volatile("ldmatrix.sync.aligned.m8n8.x4.trans.shared.b16 {%0,%1,%2,%3}, [%4];"
                 : "=r"(r[0]), "=r"(r[1]), "=r"(r[2]), "=r"(r[3]) : "r"(addr));
}
__device__ __forceinline__ void mma16816h(float (&c)[4], const uint32_t (&a)[4],
                                          uint32_t b0, uint32_t b1) {
    asm volatile("mma.sync.aligned.m16n8k16.row.col.f32.f16.f16.f32 "
                 "{%0,%1,%2,%3}, {%4,%5,%6,%7}, {%8,%9}, {%0,%1,%2,%3};"
                 : "+f"(c[0]), "+f"(c[1]), "+f"(c[2]), "+f"(c[3])
                 : "r"(a[0]), "r"(a[1]), "r"(a[2]), "r"(a[3]), "r"(b0), "r"(b1));
}
__device__ __forceinline__ void cp16(uint32_t dst, const void* src) {
    asm volatile("cp.async.cg.shared.global [%0], [%1], 16;"
                 :: "r"(dst), "l"(src) : "memory");
}
__device__ __forceinline__ void sts16(uint32_t addr, uint32_t a, uint32_t b,
                                      uint32_t c, uint32_t d) {
    asm volatile("st.shared.v4.b32 [%0], {%1, %2, %3, %4};"
                 :: "r"(addr), "r"(a), "r"(b), "r"(c), "r"(d) : "memory");
}
// split fp32 pair -> fp16 hi pair + fp16 lo pair (packed)
__device__ __forceinline__ void split2h(float x0, float x1, uint32_t& h, uint32_t& l) {
    __half2 hh = __floats2half2_rn(x0, x1);
    h = *(uint32_t*)&hh;
    float2 hf = __half22float2(hh);
    __half2 ll = __floats2half2_rn(x0 - hf.x, x1 - hf.y);
    l = *(uint32_t*)&ll;
}
__device__ __forceinline__ uint32_t cvt2h(float x0, float x1) {
    __half2 hh = __floats2half2_rn(x0, x1);
    return *(uint32_t*)&hh;
}

// ---------------- simple kernels --------------------------------------------
__global__ void gather_kernel(const int* __restrict__ nodes,
                              const float* __restrict__ emb,
                              float* __restrict__ x) {
    int idx = blockIdx.x * blockDim.x + threadIdx.x;
    if (idx >= M_TOT * (D_ / 4)) return;
    int node = idx >> 6;
    int q = idx & 63;
    int v = nodes[node];
    ((float4*)x)[idx] = ((const float4*)emb)[(size_t)v * 64 + q];
}

__global__ void zero_acc_deg() {
    int idx = blockIdx.x * blockDim.x + threadIdx.x;
    float4 z = make_float4(0.f, 0.f, 0.f, 0.f);
    ((float4*)g_acc)[idx] = z;
    if (idx < M_TOT / 4) ((float4*)g_deg)[idx] = z;
}

__global__ void scatter_kernel(const float* __restrict__ x,
                               const int* __restrict__ edges,
                               const int* __restrict__ types) {
    int gtid = blockIdx.x * blockDim.x + threadIdx.x;
    int w = gtid >> 5;
    int lane = gtid & 31;
    if (w >= B_ * E_) return;
    int b = w >> 15;
    int e = w & (E_ - 1);
    const int* eb = edges + (size_t)b * 2 * E_;
    int src = eb[e];
    int dst = eb[E_ + e];
    int r = types[(size_t)b * E_ + e];

    const float4* xs = (const float4*)(x + ((size_t)(b * N_ + src)) * D_);
    float* ap = g_acc + ((size_t)(b * N_ + dst) * R_ + r) * D_;

#pragma unroll
    for (int it = 0; it < 2; it++) {
        int q = lane + it * 32;
        float4 v = xs[q];
        asm volatile("red.global.add.v4.f32 [%0], {%1, %2, %3, %4};"
                     :: "l"(ap + q * 4), "f"(v.x), "f"(v.y), "f"(v.z), "f"(v.w)
                     : "memory");
    }
    if (lane == 0) atomicAdd(&g_deg[b * N_ + dst], 1.0f);
}

// Pre-convert + pre-swizzle W into ldmatrix-ready fp16 tile images.
// Logical B[k][n] = (k < K1) ? Wl[k][n] : Wr[k-K1][n].
// Tile (kt, nb) image: [krow 0..31][granule g 0..15] with granule swizzle
//   byte_off = krow*256 + ((g ^ (krow & 7)) * 16), covering n = nb*128 + g*8 .. +7
__global__ void bconv_kernel(const float* __restrict__ Wl,
                             const float* __restrict__ Wr) {
    int gid = blockIdx.x * blockDim.x + threadIdx.x;   // NT2*2*512
    if (gid >= NT2 * 2 * 512) return;
    int tile = gid >> 9;            // kt*2 + nb
    int rem = gid & 511;
    int krow = rem >> 4;
    int g = rem & 15;
    int kt = tile >> 1;
    int nb = tile & 1;
    int k = kt * KT2 + krow;
    int n0 = nb * 128 + g * 8;
    const float* src = (k < K1) ? (Wl + (size_t)k * D_ + n0)
                                : (Wr + (size_t)(k - K1) * D_ + n0);
    float4 v0 = ((const float4*)src)[0];
    float4 v1 = ((const float4*)src)[1];
    uint4 h;
    h.x = cvt2h(v0.x, v0.y);
    h.y = cvt2h(v0.z, v0.w);
    h.z = cvt2h(v1.x, v1.y);
    h.w = cvt2h(v1.z, v1.w);
    uint32_t off = (uint32_t)tile * 8192u + (uint32_t)krow * 256u +
                   ((uint32_t)(g ^ (krow & 7)) << 4);
    *(uint4*)(g_Bh + off) = h;
}

// ---------------- warp-MMA GEMM ----------------------------------------------
// Out[m0..+127][col0..+127] = relu?( [acc*invdeg | x](K=2304) * B + bias )
// 2-pass fp16 split: (ahi + alo) * bhi, fp32 accum via HMMA.
__global__ void __launch_bounds__(256, 2)
rgcn_gemm_mma(const float* __restrict__ X,
              const float* __restrict__ bias,
              float* __restrict__ Out,
              int do_relu) {
    extern __shared__ uint8_t smem_raw[];
    const uint32_t sbase = (smem_u32(smem_raw) + 127u) & ~127u;

    const int tid = threadIdx.x;
    const int lane = tid & 31;
    const int wid = tid >> 5;
    const int warp_m = wid & 3;      // 4 warps along M (32 rows each)
    const int warp_n = wid >> 2;     // 2 warps along N (64 cols each)
    const int bx = blockIdx.x;
    const int m0 = blockIdx.y * 128;
    const int col0 = bx * 128;

    // A fill mapping: 2 threads per row, 16 k-values each
    const int arow = tid >> 1;
    const int akb = (tid & 1) * 16;
    const float invdeg = 1.0f / fmaxf(g_deg[m0 + arow], 1.0f);
    const uint32_t a_sts = (uint32_t)arow * A_STRIDE + (uint32_t)akb * 2;

    // ldmatrix address pieces
    uint32_t a_off[2];
#pragma unroll
    for (int mt = 0; mt < 2; mt++)
        a_off[mt] = (uint32_t)(warp_m * 32 + mt * 16 + (lane & 15)) * A_STRIDE +
                    (uint32_t)((lane >> 4) * 16);
    const uint32_t krow_base = (uint32_t)((lane & 7) + ((lane >> 3) & 1) * 8);
    uint32_t gg[4];
#pragma unroll
    for (int nt2 = 0; nt2 < 4; nt2++)
        gg[nt2] = (uint32_t)(((warp_n * 8 + nt2 * 2 + (lane >> 4)) ^ (lane & 7)) << 4);

    float c[2][8][4];
#pragma unroll
    for (int mt = 0; mt < 2; mt++)
#pragma unroll
        for (int nt = 0; nt < 8; nt++)
#pragma unroll
            for (int j = 0; j < 4; j++) c[mt][nt][j] = 0.f;

    float areg[16];   // prefetched fp32 A values for the NEXT stage

    // issue global loads for stage kt into areg (A) and smem stage s (B)
    auto issue_loads = [&](int kt, int s) {
        const uint32_t st = sbase + (uint32_t)s * STAGE;
        const uint8_t* bh = g_Bh + (size_t)(kt * 2 + bx) * 8192 + tid * 16;
        cp16(st + OFF_B + tid * 16, bh);
        cp16(st + OFF_B + 4096 + tid * 16, bh + 4096);
        asm volatile("cp.async.commit_group;" ::: "memory");
        const float* asrc = (kt < NTA2)
            ? g_acc + (size_t)(m0 + arow) * K1 + kt * KT2 + akb
            : X + (size_t)(m0 + arow) * D_ + (kt - NTA2) * KT2 + akb;
#pragma unroll
        for (int q = 0; q < 4; q++) {
            float4 v = ((const float4*)asrc)[q];
            areg[q * 4 + 0] = v.x;
            areg[q * 4 + 1] = v.y;
            areg[q * 4 + 2] = v.z;
            areg[q * 4 + 3] = v.w;
        }
    };

    // split the prefetched A registers and store into smem stage s
    auto store_a = [&](int kt, int s) {
        const uint32_t st = sbase + (uint32_t)s * STAGE;
        const float scale = (kt < NTA2) ? invdeg : 1.0f;
        uint32_t hi[8], lo[8];
#pragma unroll
        for (int q = 0; q < 8; q++)
            split2h(areg[2 * q] * scale, areg[2 * q + 1] * scale, hi[q], lo[q]);
        uint32_t ad = st + a_sts;
        sts16(ad, hi[0], hi[1], hi[2], hi[3]);
        sts16(ad + 16, hi[4], hi[5], hi[6], hi[7]);
        sts16(ad + OFF_ALO, lo[0], lo[1], lo[2], lo[3]);
        sts16(ad + OFF_ALO + 16, lo[4], lo[5], lo[6], lo[7]);
    };

    auto compute = [&](int s) {
        const uint32_t st = sbase + (uint32_t)s * STAGE;
#pragma unroll
        for (int k16 = 0; k16 < 2; k16++) {
            const uint32_t kb2 = (uint32_t)(k16 * 32);          // A byte offset
            const uint32_t brow = (uint32_t)((k16 * 16) + krow_base) * 256u;
            uint32_t ah[2][4], al[2][4], bb[4][4];
            ldsm4(ah[0], st + a_off[0] + kb2);
            ldsm4(ah[1], st + a_off[1] + kb2);
            ldsm4(al[0], st + OFF_ALO + a_off[0] + kb2);
            ldsm4(al[1], st + OFF_ALO + a_off[1] + kb2);
#pragma unroll
            for (int nt2 = 0; nt2 < 4; nt2++)
                ldsm4t(bb[nt2], st + OFF_B + brow + gg[nt2]);
#pragma unroll
            for (int mt = 0; mt < 2; mt++)
#pragma unroll
                for (int nt = 0; nt < 8; nt++)
                    mma16816h(c[mt][nt], ah[mt], bb[nt >> 1][(nt & 1) * 2],
                              bb[nt >> 1][(nt & 1) * 2 + 1]);
#pragma unroll
            for (int mt = 0; mt < 2; mt++)
#pragma unroll
                for (int nt = 0; nt < 8; nt++)
                    mma16816h(c[mt][nt], al[mt], bb[nt >> 1][(nt & 1) * 2],
                              bb[nt >> 1][(nt & 1) * 2 + 1]);
        }
    };

    // prologue: fill stage 0
    issue_loads(0, 0);
    store_a(0, 0);
    asm volatile("cp.async.wait_group 0;" ::: "memory");
    __syncthreads();

#pragma unroll 1
    for (int kt = 0; kt < NT2; kt++) {
        const int s = kt & 1;
        if (kt + 1 < NT2) issue_loads(kt + 1, s ^ 1);   // LDG/cp.async in flight
        compute(s);                                     // hide latency under MMAs
        if (kt + 1 < NT2) {
            store_a(kt + 1, s ^ 1);                     // regs have landed by now
            asm volatile("cp.async.wait_group 0;" ::: "memory");
            __syncthreads();
        }
    }

    // epilogue: + bias, relu?, store fp32
    const int g = lane >> 2;
    const int tc = lane & 3;
#pragma unroll
    for (int mt = 0; mt < 2; mt++) {
        const int row = m0 + warp_m * 32 + mt * 16 + g;
#pragma unroll
        for (int nt = 0; nt < 8; nt++) {
            const int col = col0 + warp_n * 64 + nt * 8 + tc * 2;
            const float b0 = bias[col];
            const float b1 = bias[col + 1];
            float2 v0 = make_float2(c[mt][nt][0] + b0, c[mt][nt][1] + b1);
            float2 v1 = make_float2(c[mt][nt][2] + b0, c[mt][nt][3] + b1);
            if (do_relu) {
                v0.x = fmaxf(v0.x, 0.f); v0.y = fmaxf(v0.y, 0.f);
                v1.x = fmaxf(v1.x, 0.f); v1.y = fmaxf(v1.y, 0.f);
            }
            *(float2*)&Out[(size_t)row * D_ + col] = v0;
            *(float2*)&Out[(size_t)(row + 8) * D_ + col] = v1;
        }
    }
}

// ---------------- launch ----------------------------------------------------
extern "C" void kernel_launch(void* const* d_in, const int* in_sizes, int n_in,
                              void* d_out, int out_size) {
    const int*   nodes = (const int*)d_in[0];
    const int*   edges = (const int*)d_in[1];
    const int*   types = (const int*)d_in[2];
    const float* emb   = (const float*)d_in[3];
    const float* W     = (const float*)d_in[4];
    const float* Wroot = (const float*)d_in[5];
    const float* bias  = (const float*)d_in[6];
    float* out = (float*)d_out;

    cudaFuncSetAttribute(rgcn_gemm_mma,
                         cudaFuncAttributeMaxDynamicSharedMemorySize, SMEM_DYN);

    float *x0 = nullptr, *x1 = nullptr;
    cudaGetSymbolAddress((void**)&x0, g_x);
    cudaGetSymbolAddress((void**)&x1, g_y);

    gather_kernel<<<(M_TOT * (D_ / 4) + 255) / 256, 256>>>(nodes, emb, x0);

    const float* xin = x0;
    for (int l = 0; l < L_; l++) {
        zero_acc_deg<<<65536, 256>>>();
        scatter_kernel<<<(B_ * E_ * 32) / 256, 256>>>(xin, edges, types);
        bconv_kernel<<<(NT2 * 2 * 512 + 255) / 256, 256>>>(
            W + (size_t)l * R_ * D_ * D_, Wroot + (size_t)l * D_ * D_);
        float* o = (l == L_ - 1) ? out : x1;
        dim3 grid(2, M_TOT / 128);   // (2, 256)
        rgcn_gemm_mma<<<grid, 256, SMEM_DYN>>>(
            xin, bias + (size_t)l * D_, o, (l < L_ - 1) ? 1 : 0);
        xin = o;
    }
}

// round 5
// speedup vs baseline: 2.6884x; 1.0603x over previous
#include <cuda_runtime.h>
#include <cuda_fp16.h>
#include <cstdint>
#include <cstddef>

// Problem constants
#define B_   16
#define N_   2048
#define E_   32768
#define D_   256
#define R_   8
#define L_   2

#define M_TOT (B_ * N_)       // 32768 rows
#define K1    (R_ * D_)       // 2048 (relation part of K)
#define K_TOT (K1 + D_)       // 2304 total K
#define KT2   32              // K per stage
#define NT2   (K_TOT / KT2)   // 72 stages
#define NTA2  (K1 / KT2)      // 64 stages from acc, 8 from x

// ---------------- scratch (device globals; no allocation allowed) ----------
__device__ float g_x[M_TOT * D_];
__device__ float g_y[M_TOT * D_];
__device__ float g_acc[(size_t)M_TOT * K1];        // 268 MB
__device__ float g_deg[M_TOT];
// pre-converted, pre-swizzled fp16 B tiles: [kt(72)] x 16384 bytes (32k x 256n)
__device__ uint8_t g_Bh[NT2 * 16384];

// ---------------- smem geometry for the GEMM -------------------------------
#define A_STRIDE  80                       // bytes per 32-fp16 A row (64B + 16 pad)
#define SA_BYTES  (128 * A_STRIDE)         // 10240 per A split
#define OFF_ALO   SA_BYTES                 // 10240
#define OFF_B     (2 * SA_BYTES)           // 20480 (128B aligned)
#define STAGE     (OFF_B + 16384)          // 36864
#define SMEM_DYN  (2 * STAGE + 128)        // 73856

// ---------------- PTX helpers ----------------------------------------------
__device__ __forceinline__ uint32_t smem_u32(const void* p) {
    uint32_t a;
    asm("{ .reg .u64 t; cvta.to.shared.u64 t, %1; cvt.u32.u64 %0, t; }"
        : "=r"(a) : "l"(p));
    return a;
}
__device__ __forceinline__ void ldsm4(uint32_t (&r)[4], uint32_t addr) {
    asm volatile("ldmatrix.sync.aligned.m8n8.x4.shared.b16 {%0,%1,%2,%3}, [%4];"
                 : "=r"(r[0]), "=r"(r[1]), "=r"(r[2]), "=r"(r[3]) : "r"(addr));
}
__device__ __forceinline__ void ldsm4t(uint32_t (&r)[4], uint32_t addr) {
    asm volatile("ldmatrix.sync.aligned.m8n8.x4.trans.shared.b16 {%0,%1,%2,%3}, [%4];"
                 : "=r"(r[0]), "=r"(r[1]), "=r"(r[2]), "=r"(r[3]) : "r"(addr));
}
__device__ __forceinline__ void mma16816h(float (&c)[4], const uint32_t (&a)[4],
                                          uint32_t b0, uint32_t b1) {
    asm volatile("mma.sync.aligned.m16n8k16.row.col.f32.f16.f16.f32 "
                 "{%0,%1,%2,%3}, {%4,%5,%6,%7}, {%8,%9}, {%0,%1,%2,%3};"
                 : "+f"(c[0]), "+f"(c[1]), "+f"(c[2]), "+f"(c[3])
                 : "r"(a[0]), "r"(a[1]), "r"(a[2]), "r"(a[3]), "r"(b0), "r"(b1));
}
__device__ __forceinline__ void cp16(uint32_t dst, const void* src) {
    asm volatile("cp.async.cg.shared.global [%0], [%1], 16;"
                 :: "r"(dst), "l"(src) : "memory");
}
__device__ __forceinline__ void sts16(uint32_t addr, uint32_t a, uint32_t b,
                                      uint32_t c, uint32_t d) {
    asm volatile("st.shared.v4.b32 [%0], {%1, %2, %3, %4};"
                 :: "r"(addr), "r"(a), "r"(b), "r"(c), "r"(d) : "memory");
}
// split fp32 pair -> fp16 hi pair + fp16 lo pair (packed)
__device__ __forceinline__ void split2h(float x0, float x1, uint32_t& h, uint32_t& l) {
    __half2 hh = __floats2half2_rn(x0, x1);
    h = *(uint32_t*)&hh;
    float2 hf = __half22float2(hh);
    __half2 ll = __floats2half2_rn(x0 - hf.x, x1 - hf.y);
    l = *(uint32_t*)&ll;
}
__device__ __forceinline__ uint32_t cvt2h(float x0, float x1) {
    __half2 hh = __floats2half2_rn(x0, x1);
    return *(uint32_t*)&hh;
}

// ---------------- simple kernels --------------------------------------------
__global__ void gather_kernel(const int* __restrict__ nodes,
                              const float* __restrict__ emb,
                              float* __restrict__ x) {
    int idx = blockIdx.x * blockDim.x + threadIdx.x;
    if (idx >= M_TOT * (D_ / 4)) return;
    int node = idx >> 6;
    int q = idx & 63;
    int v = nodes[node];
    ((float4*)x)[idx] = ((const float4*)emb)[(size_t)v * 64 + q];
}

__global__ void zero_acc_deg() {
    int idx = blockIdx.x * blockDim.x + threadIdx.x;
    float4 z = make_float4(0.f, 0.f, 0.f, 0.f);
    ((float4*)g_acc)[idx] = z;
    if (idx < M_TOT / 4) ((float4*)g_deg)[idx] = z;
}

__global__ void scatter_kernel(const float* __restrict__ x,
                               const int* __restrict__ edges,
                               const int* __restrict__ types) {
    int gtid = blockIdx.x * blockDim.x + threadIdx.x;
    int w = gtid >> 5;
    int lane = gtid & 31;
    if (w >= B_ * E_) return;
    int b = w >> 15;
    int e = w & (E_ - 1);
    const int* eb = edges + (size_t)b * 2 * E_;
    int src = eb[e];
    int dst = eb[E_ + e];
    int r = types[(size_t)b * E_ + e];

    const float4* xs = (const float4*)(x + ((size_t)(b * N_ + src)) * D_);
    float* ap = g_acc + ((size_t)(b * N_ + dst) * R_ + r) * D_;

#pragma unroll
    for (int it = 0; it < 2; it++) {
        int q = lane + it * 32;
        float4 v = xs[q];
        asm volatile("red.global.add.v4.f32 [%0], {%1, %2, %3, %4};"
                     :: "l"(ap + q * 4), "f"(v.x), "f"(v.y), "f"(v.z), "f"(v.w)
                     : "memory");
    }
    if (lane == 0) atomicAdd(&g_deg[b * N_ + dst], 1.0f);
}

// Pre-convert + pre-swizzle W into ldmatrix-ready fp16 tile images.
// Logical B[k][n] = (k < K1) ? Wl[k][n] : Wr[k-K1][n].
// Tile kt image: [krow 0..31][granule g 0..31], row stride 512B,
//   byte_off = krow*512 + ((g ^ (krow & 7)) * 16), granule g covers n = g*8..+7
__global__ void bconv_kernel(const float* __restrict__ Wl,
                             const float* __restrict__ Wr) {
    int gid = blockIdx.x * blockDim.x + threadIdx.x;   // NT2*32*32
    if (gid >= NT2 * 1024) return;
    int kt = gid >> 10;
    int rem = gid & 1023;
    int krow = rem >> 5;
    int g = rem & 31;
    int k = kt * KT2 + krow;
    int n0 = g * 8;
    const float* src = (k < K1) ? (Wl + (size_t)k * D_ + n0)
                                : (Wr + (size_t)(k - K1) * D_ + n0);
    float4 v0 = ((const float4*)src)[0];
    float4 v1 = ((const float4*)src)[1];
    uint4 h;
    h.x = cvt2h(v0.x, v0.y);
    h.y = cvt2h(v0.z, v0.w);
    h.z = cvt2h(v1.x, v1.y);
    h.w = cvt2h(v1.z, v1.w);
    uint32_t off = (uint32_t)kt * 16384u + (uint32_t)krow * 512u +
                   ((uint32_t)(g ^ (krow & 7)) << 4);
    *(uint4*)(g_Bh + off) = h;
}

// ---------------- warp-MMA GEMM ----------------------------------------------
// CTA: 128 rows x FULL 256 cols, 512 threads (16 warps: 4 M x 4 N).
// Out[m0..+127][:] = relu?( (acc@Wcat)/deg + x@Wroot + bias )
// 2-pass fp16 split on A; 1/deg applied to accumulators after the acc K-stages.
__global__ void __launch_bounds__(512, 1)
rgcn_gemm_mma(const float* __restrict__ X,
              const float* __restrict__ bias,
              float* __restrict__ Out,
              int do_relu) {
    extern __shared__ uint8_t smem_raw[];
    const uint32_t sbase = (smem_u32(smem_raw) + 127u) & ~127u;

    const int tid = threadIdx.x;
    const int lane = tid & 31;
    const int wid = tid >> 5;
    const int warp_m = wid & 3;      // 4 warps along M (32 rows each)
    const int warp_n = wid >> 2;     // 4 warps along N (64 cols each)
    const int m0 = blockIdx.x * 128;

    // A fill mapping: 4 threads per row, 8 k-values each
    const int arow = tid >> 2;
    const int akb = (tid & 3) * 8;
    const uint32_t a_sts = (uint32_t)arow * A_STRIDE + (uint32_t)akb * 2;

    // per-thread 1/deg for the 4 accumulator row groups
    const int g = lane >> 2;
    const int tc = lane & 3;
    float invd[2][2];
#pragma unroll
    for (int mt = 0; mt < 2; mt++)
#pragma unroll
        for (int h = 0; h < 2; h++)
            invd[mt][h] = 1.0f /
                fmaxf(g_deg[m0 + warp_m * 32 + mt * 16 + g + h * 8], 1.0f);

    // ldmatrix address pieces
    uint32_t a_off[2];
#pragma unroll
    for (int mt = 0; mt < 2; mt++)
        a_off[mt] = (uint32_t)(warp_m * 32 + mt * 16 + (lane & 15)) * A_STRIDE +
                    (uint32_t)((lane >> 4) * 16);
    const uint32_t krow_base = (uint32_t)((lane & 7) + ((lane >> 3) & 1) * 8);
    uint32_t gg[4];
#pragma unroll
    for (int nt2 = 0; nt2 < 4; nt2++)
        gg[nt2] = (uint32_t)(((warp_n * 8 + nt2 * 2 + (lane >> 4)) ^ (lane & 7)) << 4);

    float c[2][8][4];
#pragma unroll
    for (int mt = 0; mt < 2; mt++)
#pragma unroll
        for (int nt = 0; nt < 8; nt++)
#pragma unroll
            for (int j = 0; j < 4; j++) c[mt][nt][j] = 0.f;

    float areg[8];   // prefetched fp32 A values for the NEXT stage

    // issue global loads for stage kt: B via cp.async into smem stage s, A into regs
    auto issue_loads = [&](int kt, int s) {
        const uint32_t st = sbase + (uint32_t)s * STAGE;
        const uint8_t* bh = g_Bh + (size_t)kt * 16384 + tid * 16;
        cp16(st + OFF_B + tid * 16, bh);
        cp16(st + OFF_B + 8192 + tid * 16, bh + 8192);
        asm volatile("cp.async.commit_group;" ::: "memory");
        const float* asrc = (kt < NTA2)
            ? g_acc + (size_t)(m0 + arow) * K1 + kt * KT2 + akb
            : X + (size_t)(m0 + arow) * D_ + (kt - NTA2) * KT2 + akb;
        float4 v0 = ((const float4*)asrc)[0];
        float4 v1 = ((const float4*)asrc)[1];
        areg[0] = v0.x; areg[1] = v0.y; areg[2] = v0.z; areg[3] = v0.w;
        areg[4] = v1.x; areg[5] = v1.y; areg[6] = v1.z; areg[7] = v1.w;
    };

    // split the prefetched A registers and store into smem stage s
    auto store_a = [&](int s) {
        const uint32_t st = sbase + (uint32_t)s * STAGE;
        uint32_t hi[4], lo[4];
#pragma unroll
        for (int q = 0; q < 4; q++)
            split2h(areg[2 * q], areg[2 * q + 1], hi[q], lo[q]);
        uint32_t ad = st + a_sts;
        sts16(ad, hi[0], hi[1], hi[2], hi[3]);
        sts16(ad + OFF_ALO, lo[0], lo[1], lo[2], lo[3]);
    };

    auto compute = [&](int s) {
        const uint32_t st = sbase + (uint32_t)s * STAGE;
#pragma unroll
        for (int k16 = 0; k16 < 2; k16++) {
            const uint32_t kb2 = (uint32_t)(k16 * 32);          // A byte offset
            const uint32_t brow = (uint32_t)((k16 * 16) + krow_base) * 512u;
            uint32_t ah[2][4], al[2][4], bb[4][4];
            ldsm4(ah[0], st + a_off[0] + kb2);
            ldsm4(ah[1], st + a_off[1] + kb2);
            ldsm4(al[0], st + OFF_ALO + a_off[0] + kb2);
            ldsm4(al[1], st + OFF_ALO + a_off[1] + kb2);
#pragma unroll
            for (int nt2 = 0; nt2 < 4; nt2++)
                ldsm4t(bb[nt2], st + OFF_B + brow + gg[nt2]);
#pragma unroll
            for (int mt = 0; mt < 2; mt++)
#pragma unroll
                for (int nt = 0; nt < 8; nt++)
                    mma16816h(c[mt][nt], ah[mt], bb[nt >> 1][(nt & 1) * 2],
                              bb[nt >> 1][(nt & 1) * 2 + 1]);
#pragma unroll
            for (int mt = 0; mt < 2; mt++)
#pragma unroll
                for (int nt = 0; nt < 8; nt++)
                    mma16816h(c[mt][nt], al[mt], bb[nt >> 1][(nt & 1) * 2],
                              bb[nt >> 1][(nt & 1) * 2 + 1]);
        }
    };

    // prologue: fill stage 0
    issue_loads(0, 0);
    store_a(0);
    asm volatile("cp.async.wait_group 0;" ::: "memory");
    __syncthreads();

#pragma unroll 1
    for (int kt = 0; kt < NT2; kt++) {
        const int s = kt & 1;
        if (kt + 1 < NT2) issue_loads(kt + 1, s ^ 1);   // LDG/cp.async in flight
        compute(s);                                     // hide latency under MMAs
        if (kt == NTA2 - 1) {
            // all relation-K consumed: scale accumulators by 1/max(deg,1)
#pragma unroll
            for (int mt = 0; mt < 2; mt++)
#pragma unroll
                for (int nt = 0; nt < 8; nt++) {
                    c[mt][nt][0] *= invd[mt][0];
                    c[mt][nt][1] *= invd[mt][0];
                    c[mt][nt][2] *= invd[mt][1];
                    c[mt][nt][3] *= invd[mt][1];
                }
        }
        if (kt + 1 < NT2) {
            store_a(s ^ 1);                             // regs have landed by now
            asm volatile("cp.async.wait_group 0;" ::: "memory");
            __syncthreads();
        }
    }

    // epilogue: + bias, relu?, store fp32
#pragma unroll
    for (int mt = 0; mt < 2; mt++) {
        const int row = m0 + warp_m * 32 + mt * 16 + g;
#pragma unroll
        for (int nt = 0; nt < 8; nt++) {
            const int col = warp_n * 64 + nt * 8 + tc * 2;
            const float b0 = bias[col];
            const float b1 = bias[col + 1];
            float2 v0 = make_float2(c[mt][nt][0] + b0, c[mt][nt][1] + b1);
            float2 v1 = make_float2(c[mt][nt][2] + b0, c[mt][nt][3] + b1);
            if (do_relu) {
                v0.x = fmaxf(v0.x, 0.f); v0.y = fmaxf(v0.y, 0.f);
                v1.x = fmaxf(v1.x, 0.f); v1.y = fmaxf(v1.y, 0.f);
            }
            *(float2*)&Out[(size_t)row * D_ + col] = v0;
            *(float2*)&Out[(size_t)(row + 8) * D_ + col] = v1;
        }
    }
}

// ---------------- launch ----------------------------------------------------
extern "C" void kernel_launch(void* const* d_in, const int* in_sizes, int n_in,
                              void* d_out, int out_size) {
    const int*   nodes = (const int*)d_in[0];
    const int*   edges = (const int*)d_in[1];
    const int*   types = (const int*)d_in[2];
    const float* emb   = (const float*)d_in[3];
    const float* W     = (const float*)d_in[4];
    const float* Wroot = (const float*)d_in[5];
    const float* bias  = (const float*)d_in[6];
    float* out = (float*)d_out;

    cudaFuncSetAttribute(rgcn_gemm_mma,
                         cudaFuncAttributeMaxDynamicSharedMemorySize, SMEM_DYN);

    float *x0 = nullptr, *x1 = nullptr;
    cudaGetSymbolAddress((void**)&x0, g_x);
    cudaGetSymbolAddress((void**)&x1, g_y);

    gather_kernel<<<(M_TOT * (D_ / 4) + 255) / 256, 256>>>(nodes, emb, x0);

    const float* xin = x0;
    for (int l = 0; l < L_; l++) {
        zero_acc_deg<<<65536, 256>>>();
        scatter_kernel<<<(B_ * E_ * 32) / 256, 256>>>(xin, edges, types);
        bconv_kernel<<<(NT2 * 1024 + 255) / 256, 256>>>(
            W + (size_t)l * R_ * D_ * D_, Wroot + (size_t)l * D_ * D_);
        float* o = (l == L_ - 1) ? out : x1;
        rgcn_gemm_mma<<<M_TOT / 128, 512, SMEM_DYN>>>(
            xin, bias + (size_t)l * D_, o, (l < L_ - 1) ? 1 : 0);
        xin = o;
    }
}